// round 1
// baseline (speedup 1.0000x reference)
#include <cuda_runtime.h>
#include <cstdint>
#include <cstddef>

// Ridge_51178830299316 — recursive least squares (Sherman-Morrison) formulation.
//
// Reference: pred[b, k+1] = x_{k+1}^T (I + sum_{t<=k} x_t x_t^T)^{-1} (sum_{t<=k} y_t x_t)
// RLS recursion (M = A^{-1}, w = A^{-1} b):
//   v = M x_k ; s = x_k.v ; e = y_k - x_k.w ; coef = e/(1+s)
//   w += coef * v ; M -= (v v^T)/(1+s) ; pred[k+1] = x_{k+1}.w
//
// Implementation: 1 CTA per batch (32 CTAs), 640 threads.
//   - Threads 0..511 ("P" role): M resident in registers, 32 f32 each
//     (row = tid&127, column-block cb = tid>>7). Each iteration fuses the
//     (deferred) rank-1 update with the matvec against x_{k+1}:
//        m[j] -= u_{k-1}[row] * v_{k-1}[j] ;  p += m[j] * x_{k+1}[j]
//     producing raw partials of M_{k-1} x_{k+1}.
//   - Threads 512..639 ("S" role): scalar phase. Corrects the stale raw
//     matvec: v_k = raw(M_{k-2} x_k) - u_{k-1} * (v_{k-1}.x_k), then one
//     4-value warp reduction (s, x_k.w, v_k.x_{k+1}, x_{k+1}.w), scalar
//     math, w update (w kept in registers of S threads), and writes
//     u_k, v_k into the alternate smem buffer. pred folds in as
//     ewn + coef*d — no second reduction round.
//   Because P_k depends only on S_{k-1}/P_{k-1} outputs and S_k only on
//   P_{k-1}/S_{k-1} outputs, P and S overlap inside one iteration with a
//   single full __syncthreads at the bottom (plus one named barrier
//   private to the 4 S warps).

#define BATCH     32
#define NPTS      256
#define DIM       128
#define PTHREADS  512
#define TOTTHREADS 640

struct SMLayout {
    float  xs[NPTS][DIM];     // batch data, 128 KB
    float  ts[NPTS];          // targets
    float  part[2][4][DIM];   // matvec partials, double-buffered
    float  v[2][DIM];         // v_k, double-buffered
    float  u[2][DIM];         // u_k = v_k/(1+s), double-buffered
    float4 red[4];            // per-warp reduction results (s, ew, d, ewn)
};

__global__ void __launch_bounds__(TOTTHREADS, 1)
ridge_rls_kernel(const float* __restrict__ data,
                 const float* __restrict__ targets,
                 float* __restrict__ out)
{
    extern __shared__ char smem_raw[];
    SMLayout& sm = *reinterpret_cast<SMLayout*>(smem_raw);
    const int tid = threadIdx.x;
    const int b   = blockIdx.x;

    // ---- Stage batch data + targets into shared memory (float4 copies) ----
    {
        const float4* src = reinterpret_cast<const float4*>(data + (size_t)b * NPTS * DIM);
        float4* dst = reinterpret_cast<float4*>(&sm.xs[0][0]);
        #pragma unroll 4
        for (int idx = tid; idx < NPTS * DIM / 4; idx += TOTTHREADS)
            dst[idx] = src[idx];
        if (tid < NPTS / 4) {
            reinterpret_cast<float4*>(sm.ts)[tid] =
                reinterpret_cast<const float4*>(targets + (size_t)b * NPTS)[tid];
        }
    }
    __syncthreads();

    // ---- Prologue: M_{-1} = I, so raw partials for k=0 are just x_0. ----
    if (tid < DIM) {
        sm.part[0][0][tid] = sm.xs[0][tid];
        sm.part[0][1][tid] = 0.f;
        sm.part[0][2][tid] = 0.f;
        sm.part[0][3][tid] = 0.f;
        sm.v[0][tid] = 0.f;   // (u_{-1}, v_{-1}) = 0 -> P_0 applies a no-op update
        sm.u[0][tid] = 0.f;
    }
    if (tid == 0) out[(size_t)b * NPTS] = 0.f;   // pred[:,0] = 0
    __syncthreads();

    // ---- Persistent per-thread state ----
    const int row = tid & 127;
    const int cb  = (tid >> 7) & 3;       // valid for P threads only
    float m[32];
    if (tid < PTHREADS) {
        #pragma unroll
        for (int j = 0; j < 32; j++)
            m[j] = (cb * 32 + j == row) ? 1.0f : 0.0f;   // M = (1/lambda) I, lambda=1
    }
    float w_reg  = 0.f;   // S threads: w[i]
    float d_prev = 0.f;   // S threads: d_{k-1} = v_{k-1} . x_k (replicated)

    int buf = 0;
    #pragma unroll 1
    for (int k = 0; k < NPTS - 1; k++) {
        if (tid < PTHREADS) {
            // ======== P role: deferred rank-1 update fused with matvec ========
            const float nu = -sm.u[buf][row];
            const float4* vv = reinterpret_cast<const float4*>(&sm.v[buf][cb * 32]);
            const float4* xx = reinterpret_cast<const float4*>(&sm.xs[k + 1][cb * 32]);
            float p0 = 0.f, p1 = 0.f, p2 = 0.f, p3 = 0.f;
            #pragma unroll
            for (int q = 0; q < 8; q++) {
                const float4 v4 = vv[q];   // broadcast (same addr across warp)
                const float4 x4 = xx[q];   // broadcast
                m[4*q+0] = fmaf(nu, v4.x, m[4*q+0]); p0 = fmaf(m[4*q+0], x4.x, p0);
                m[4*q+1] = fmaf(nu, v4.y, m[4*q+1]); p1 = fmaf(m[4*q+1], x4.y, p1);
                m[4*q+2] = fmaf(nu, v4.z, m[4*q+2]); p2 = fmaf(m[4*q+2], x4.z, p2);
                m[4*q+3] = fmaf(nu, v4.w, m[4*q+3]); p3 = fmaf(m[4*q+3], x4.w, p3);
            }
            sm.part[buf ^ 1][cb][row] = (p0 + p1) + (p2 + p3);
        } else {
            // ======== S role: scalar recursion ========
            const int i    = tid - PTHREADS;   // 0..127
            const int lane = i & 31;
            const int wi   = i >> 5;
            // v_k[i] = sum_cb raw_part - u_{k-1}[i] * d_{k-1}
            float vi = ((sm.part[buf][0][i] + sm.part[buf][1][i])
                      + (sm.part[buf][2][i] + sm.part[buf][3][i]))
                      - sm.u[buf][i] * d_prev;
            const float xk = sm.xs[k][i];
            const float xn = sm.xs[k + 1][i];
            float a_s = xk * vi;       // -> s   = x_k . v_k
            float a_e = xk * w_reg;    // -> ew  = x_k . w_{k-1}
            float a_d = xn * vi;       // -> d_k = x_{k+1} . v_k
            float a_p = xn * w_reg;    // -> ewn = x_{k+1} . w_{k-1}
            #pragma unroll
            for (int off = 16; off > 0; off >>= 1) {
                a_s += __shfl_xor_sync(0xffffffffu, a_s, off);
                a_e += __shfl_xor_sync(0xffffffffu, a_e, off);
                a_d += __shfl_xor_sync(0xffffffffu, a_d, off);
                a_p += __shfl_xor_sync(0xffffffffu, a_p, off);
            }
            if (lane == 0) sm.red[wi] = make_float4(a_s, a_e, a_d, a_p);
            asm volatile("bar.sync 1, 128;" ::: "memory");   // S warps only
            const float4 r0 = sm.red[0], r1 = sm.red[1], r2 = sm.red[2], r3 = sm.red[3];
            const float s   = (r0.x + r1.x) + (r2.x + r3.x);
            const float ew  = (r0.y + r1.y) + (r2.y + r3.y);
            const float d   = (r0.z + r1.z) + (r2.z + r3.z);
            const float ewn = (r0.w + r1.w) + (r2.w + r3.w);
            const float inv  = 1.0f / (1.0f + s);
            const float coef = (sm.ts[k] - ew) * inv;
            w_reg = fmaf(coef, vi, w_reg);
            sm.v[buf ^ 1][i] = vi;
            sm.u[buf ^ 1][i] = inv * vi;
            if (i == 0)
                out[(size_t)b * NPTS + k + 1] = fmaf(coef, d, ewn);  // x_{k+1}.w_k
            d_prev = d;
        }
        __syncthreads();
        buf ^= 1;
    }
}

extern "C" void kernel_launch(void* const* d_in, const int* in_sizes, int n_in,
                              void* d_out, int out_size)
{
    const float* data    = (const float*)d_in[0];   // [32, 256, 128] f32
    const float* targets = (const float*)d_in[1];   // [32, 256] f32
    float* out = (float*)d_out;                     // [32, 256] f32

    const size_t smem_bytes = sizeof(SMLayout);
    cudaFuncSetAttribute(ridge_rls_kernel,
                         cudaFuncAttributeMaxDynamicSharedMemorySize,
                         (int)smem_bytes);
    ridge_rls_kernel<<<BATCH, TOTTHREADS, smem_bytes>>>(data, targets, out);
}

// round 2
// speedup vs baseline: 1.0149x; 1.0149x over previous
#include <cuda_runtime.h>
#include <cstdint>
#include <cstddef>

// Ridge_51178830299316 — recursive least squares (Sherman-Morrison), round 2.
//
//   v = M x_k ; s = x_k.v ; e = y_k - x_k.w ; coef = e/(1+s)
//   w += coef * v ; M -= (v v^T)/(1+s) ; pred[k+1] = x_{k+1}.w
//
// 1 CTA per batch (32 CTAs), 544 threads:
//  - P role (tid 0..511): M resident in registers as 16 packed f32x2 (64-bit)
//    values per thread. Deferred rank-1 update fused with next matvec using
//    fma.rn.f32x2 -> 32 packed FMAs per thread per step (half the issue count
//    of scalar FFMA). Partials stored transposed: part[row][cb].
//  - S role (tid 512..543, ONE warp): each lane owns 4 consecutive rows.
//    Corrects the stale matvec (v_k = raw - u_{k-1} * d_{k-1}), computes the
//    four dot products (s, x_k.w, v_k.x_{k+1}, x_{k+1}.w) with a single
//    butterfly shfl.xor reduction that broadcasts totals to every lane —
//    no named barrier, no smem round trip. w kept in 4 registers per lane.
//    pred folds in as ewn + coef*d.
//  One __syncthreads per step; P_k and S_k are mutually independent.

#define BATCH     32
#define NPTS      256
#define DIM       128
#define PTHREADS  512
#define TOT       544

#define FMA2(d, a, bb, c) \
    asm("fma.rn.f32x2 %0, %1, %2, %3;" : "=l"(d) : "l"(a), "l"(bb), "l"(c))

struct SMLayout {
    float xs[NPTS][DIM];      // 128 KB batch data
    float ts[NPTS];           // targets
    float part[2][DIM][4];    // matvec partials, TRANSPOSED layout, dbl-buffered
    float v[2][DIM];          // v_k
    float u[2][DIM];          // u_k = v_k/(1+s)
};

__global__ void __launch_bounds__(TOT, 1)
ridge_rls_kernel(const float* __restrict__ data,
                 const float* __restrict__ targets,
                 float* __restrict__ out)
{
    extern __shared__ char smem_raw[];
    SMLayout& sm = *reinterpret_cast<SMLayout*>(smem_raw);
    const int tid = threadIdx.x;
    const int b   = blockIdx.x;

    // ---- Stage batch data + targets into shared memory ----
    {
        const float4* src = reinterpret_cast<const float4*>(data + (size_t)b * NPTS * DIM);
        float4* dst = reinterpret_cast<float4*>(&sm.xs[0][0]);
        for (int idx = tid; idx < NPTS * DIM / 4; idx += TOT)
            dst[idx] = src[idx];
        if (tid < NPTS / 4)
            reinterpret_cast<float4*>(sm.ts)[tid] =
                reinterpret_cast<const float4*>(targets + (size_t)b * NPTS)[tid];
    }
    __syncthreads();

    // ---- Prologue: M_{-1} = I -> raw partials for k=0 are x_0 itself ----
    if (tid < DIM) {
        *reinterpret_cast<float4*>(sm.part[0][tid]) =
            make_float4(sm.xs[0][tid], 0.f, 0.f, 0.f);
        sm.v[0][tid] = 0.f;     // (u_{-1}, v_{-1}) = 0 -> no-op update at k=0
        sm.u[0][tid] = 0.f;
    }
    if (tid == 0) out[(size_t)b * NPTS] = 0.f;    // pred[:,0] = 0
    __syncthreads();

    // ---- P-thread persistent state: M as packed f32x2 pairs ----
    const int row = tid & 127;
    const int cb  = (tid >> 7) & 3;
    unsigned long long m[16];
    if (tid < PTHREADS) {
        #pragma unroll
        for (int j = 0; j < 16; j++) {
            unsigned lo = (cb * 32 + 2 * j     == row) ? 0x3f800000u : 0u;
            unsigned hi = (cb * 32 + 2 * j + 1 == row) ? 0x3f800000u : 0u;
            m[j] = ((unsigned long long)hi << 32) | lo;   // M = I (lambda = 1)
        }
    }

    // ---- S-lane persistent state (4 rows per lane) ----
    const int lane = tid - PTHREADS;           // 0..31 for the S warp
    const int i0   = lane * 4;
    float w0 = 0.f, w1 = 0.f, w2 = 0.f, w3 = 0.f;
    float d_prev = 0.f;

    int buf = 0;
    #pragma unroll 1
    for (int k = 0; k < NPTS - 1; k++) {
        if (tid < PTHREADS) {
            // ===== P: deferred rank-1 update fused with matvec (f32x2) =====
            const float nu = -sm.u[buf][row];
            unsigned long long nn;
            asm("mov.b64 %0, {%1, %1};" : "=l"(nn) : "r"(__float_as_uint(nu)));
            const ulonglong2* vv =
                reinterpret_cast<const ulonglong2*>(&sm.v[buf][cb * 32]);
            const ulonglong2* xx =
                reinterpret_cast<const ulonglong2*>(&sm.xs[k + 1][cb * 32]);
            unsigned long long pA = 0ull, pB = 0ull;   // packed (0,0) accumulators
            #pragma unroll
            for (int q = 0; q < 8; q++) {
                const ulonglong2 v4 = vv[q];   // warp-broadcast
                const ulonglong2 x4 = xx[q];   // warp-broadcast
                FMA2(m[2*q],   nn,       v4.x, m[2*q]);
                FMA2(pA,       m[2*q],   x4.x, pA);
                FMA2(m[2*q+1], nn,       v4.y, m[2*q+1]);
                FMA2(pB,       m[2*q+1], x4.y, pB);
            }
            const float pa0 = __uint_as_float((unsigned)pA);
            const float pa1 = __uint_as_float((unsigned)(pA >> 32));
            const float pb0 = __uint_as_float((unsigned)pB);
            const float pb1 = __uint_as_float((unsigned)(pB >> 32));
            sm.part[buf ^ 1][row][cb] = (pa0 + pa1) + (pb0 + pb1);
        } else {
            // ===== S: scalar recursion, one warp, 4 rows per lane =====
            const float4 pr0 = *reinterpret_cast<const float4*>(sm.part[buf][i0 + 0]);
            const float4 pr1 = *reinterpret_cast<const float4*>(sm.part[buf][i0 + 1]);
            const float4 pr2 = *reinterpret_cast<const float4*>(sm.part[buf][i0 + 2]);
            const float4 pr3 = *reinterpret_cast<const float4*>(sm.part[buf][i0 + 3]);
            const float4 u4  = *reinterpret_cast<const float4*>(&sm.u[buf][i0]);
            const float4 xk  = *reinterpret_cast<const float4*>(&sm.xs[k][i0]);
            const float4 xn  = *reinterpret_cast<const float4*>(&sm.xs[k + 1][i0]);

            const float v0 = (pr0.x + pr0.y) + (pr0.z + pr0.w) - u4.x * d_prev;
            const float v1 = (pr1.x + pr1.y) + (pr1.z + pr1.w) - u4.y * d_prev;
            const float v2 = (pr2.x + pr2.y) + (pr2.z + pr2.w) - u4.z * d_prev;
            const float v3 = (pr3.x + pr3.y) + (pr3.z + pr3.w) - u4.w * d_prev;

            float a_s = (xk.x * v0 + xk.y * v1) + (xk.z * v2 + xk.w * v3);
            float a_e = (xk.x * w0 + xk.y * w1) + (xk.z * w2 + xk.w * w3);
            float a_d = (xn.x * v0 + xn.y * v1) + (xn.z * v2 + xn.w * v3);
            float a_p = (xn.x * w0 + xn.y * w1) + (xn.z * w2 + xn.w * w3);

            #pragma unroll
            for (int off = 16; off > 0; off >>= 1) {
                a_s += __shfl_xor_sync(0xffffffffu, a_s, off);
                a_e += __shfl_xor_sync(0xffffffffu, a_e, off);
                a_d += __shfl_xor_sync(0xffffffffu, a_d, off);
                a_p += __shfl_xor_sync(0xffffffffu, a_p, off);
            }
            // butterfly -> every lane holds the totals; no barrier needed
            const float inv  = 1.0f / (1.0f + a_s);
            const float coef = (sm.ts[k] - a_e) * inv;
            w0 = fmaf(coef, v0, w0);
            w1 = fmaf(coef, v1, w1);
            w2 = fmaf(coef, v2, w2);
            w3 = fmaf(coef, v3, w3);
            *reinterpret_cast<float4*>(&sm.v[buf ^ 1][i0]) =
                make_float4(v0, v1, v2, v3);
            *reinterpret_cast<float4*>(&sm.u[buf ^ 1][i0]) =
                make_float4(inv * v0, inv * v1, inv * v2, inv * v3);
            if (lane == 0)
                out[(size_t)b * NPTS + k + 1] = fmaf(coef, a_d, a_p);
            d_prev = a_d;
        }
        __syncthreads();
        buf ^= 1;
    }
}

extern "C" void kernel_launch(void* const* d_in, const int* in_sizes, int n_in,
                              void* d_out, int out_size)
{
    const float* data    = (const float*)d_in[0];   // [32, 256, 128] f32
    const float* targets = (const float*)d_in[1];   // [32, 256]      f32
    float* out = (float*)d_out;                     // [32, 256]      f32

    const size_t smem_bytes = sizeof(SMLayout);
    cudaFuncSetAttribute(ridge_rls_kernel,
                         cudaFuncAttributeMaxDynamicSharedMemorySize,
                         (int)smem_bytes);
    ridge_rls_kernel<<<BATCH, TOT, smem_bytes>>>(data, targets, out);
}

// round 4
// speedup vs baseline: 1.0343x; 1.0191x over previous
#include <cuda_runtime.h>
#include <cstdint>
#include <cstddef>

// Ridge_51178830299316 — rank-2 blocked recursive least squares (Woodbury), round 3 (resubmit; prior bench was an infra failure).
//
// Per block t (data points k=2t, k+1):
//   p = M x_k ; q = M x_{k+1}   (M = A^{-1} before the block)
//   s1 = x_k.p ; c = x_k.q ; inv1 = 1/(1+s1) ; cc = c*inv1
//   v = q - cc*p ; t2 = s2 - c*cc ; inv2 = 1/(1+t2)
//   coef0 = (y_k - x_k.w)*inv1 ;  pred[k+1] = x_{k+1}.w + coef0*c
//   coef1 = (y_{k+1} - pred[k+1])*inv2
//   pred[k+2] = x_{k+2}.w + coef0*d1 + coef1*(d2 - cc*d1)
//   w += coef0*p + coef1*v ;  M -= inv1*p p^T + inv2*v v^T
//
// 1 CTA / batch, 544 threads. P threads (0..511) hold M in registers as 16
// packed f32x2; each iteration applies the PREVIOUS block's rank-2 update
// fused with two matvecs (x_{2t+2}, x_{2t+3}) -> raw partials one block
// stale. S warp (512..543, 4 rows/lane) corrects staleness with register-
// resident (p, v, 4 scalars), does ONE 10-value butterfly reduce, scalar
// math, both predictions, w update. One __syncthreads per TWO steps.

#define BATCH 32
#define NPTS  256
#define DIM   128
#define PTHREADS 512
#define TOT   544
#define NBLK  128            // blocks of 2 steps (x padded with 2 zero rows)

#define FMA2(d, a, bb, c) \
    asm("fma.rn.f32x2 %0, %1, %2, %3;" : "=l"(d) : "l"(a), "l"(bb), "l"(c))

struct SMLayout {
    float xs[NPTS + 2][DIM];     // padded with 2 zero rows
    float ts[NPTS];
    float part[2][2][DIM][4];    // [buf][matvec 0/1][row][cb]
    float pc[2][DIM];            // column-side p
    float vc[2][DIM];            // column-side v
    float au[2][DIM];            // inv1 * p  (row-side)
    float bu[2][DIM];            // inv2 * v  (row-side)
};

__device__ __forceinline__ float ull_lo(unsigned long long x) {
    return __uint_as_float((unsigned)x);
}
__device__ __forceinline__ float ull_hi(unsigned long long x) {
    return __uint_as_float((unsigned)(x >> 32));
}

__global__ void __launch_bounds__(TOT, 1)
ridge_rls2_kernel(const float* __restrict__ data,
                  const float* __restrict__ targets,
                  float* __restrict__ out)
{
    extern __shared__ char smem_raw[];
    SMLayout& sm = *reinterpret_cast<SMLayout*>(smem_raw);
    const int tid = threadIdx.x;
    const int b   = blockIdx.x;

    // ---- Stage inputs ----
    {
        const float4* src = reinterpret_cast<const float4*>(data + (size_t)b * NPTS * DIM);
        float4* dst = reinterpret_cast<float4*>(&sm.xs[0][0]);
        for (int idx = tid; idx < NPTS * DIM / 4; idx += TOT)
            dst[idx] = src[idx];
        // zero the 2 padding rows
        if (tid < 2 * DIM / 4)
            reinterpret_cast<float4*>(&sm.xs[NPTS][0])[tid] =
                make_float4(0.f, 0.f, 0.f, 0.f);
        if (tid < NPTS / 4)
            reinterpret_cast<float4*>(sm.ts)[tid] =
                reinterpret_cast<const float4*>(targets + (size_t)b * NPTS)[tid];
    }
    __syncthreads();

    // ---- Prologue: raw partials for block 0 are I*x_0, I*x_1 ----
    if (tid < DIM) {
        *reinterpret_cast<float4*>(sm.part[0][0][tid]) =
            make_float4(sm.xs[0][tid], 0.f, 0.f, 0.f);
        *reinterpret_cast<float4*>(sm.part[0][1][tid]) =
            make_float4(sm.xs[1][tid], 0.f, 0.f, 0.f);
        sm.pc[0][tid] = 0.f;  sm.vc[0][tid] = 0.f;   // block -1 update = 0
        sm.au[0][tid] = 0.f;  sm.bu[0][tid] = 0.f;
    }
    if (tid == 0) out[(size_t)b * NPTS] = 0.f;
    __syncthreads();

    // ---- P persistent state: M = I as packed f32x2 ----
    const int row = tid & 127;
    const int cb  = (tid >> 7) & 3;
    unsigned long long m[16];
    if (tid < PTHREADS) {
        #pragma unroll
        for (int j = 0; j < 16; j++) {
            unsigned lo = (cb * 32 + 2 * j     == row) ? 0x3f800000u : 0u;
            unsigned hi = (cb * 32 + 2 * j + 1 == row) ? 0x3f800000u : 0u;
            m[j] = ((unsigned long long)hi << 32) | lo;
        }
    }

    // ---- S persistent state (4 rows per lane) ----
    const int lane = tid - PTHREADS;
    const int i0   = lane * 4;
    float w0 = 0.f, w1 = 0.f, w2 = 0.f, w3 = 0.f;       // w rows
    float pp0 = 0.f, pp1 = 0.f, pp2 = 0.f, pp3 = 0.f;   // prev block p
    float pv0 = 0.f, pv1 = 0.f, pv2 = 0.f, pv3 = 0.f;   // prev block v
    float cp0 = 0.f, cv0 = 0.f, cp1 = 0.f, cv1 = 0.f;   // staleness corr

    int buf = 0;
    #pragma unroll 1
    for (int t = 0; t < NBLK; t++) {
        const int k = 2 * t;
        if (tid < PTHREADS) {
            // ===== P: rank-2 update (prev block) fused with 2 matvecs =====
            const float a1 = -sm.au[buf][row];
            const float a2 = -sm.bu[buf][row];
            unsigned long long nn1, nn2;
            asm("mov.b64 %0, {%1, %1};" : "=l"(nn1) : "r"(__float_as_uint(a1)));
            asm("mov.b64 %0, {%1, %1};" : "=l"(nn2) : "r"(__float_as_uint(a2)));
            const ulonglong2* pcp =
                reinterpret_cast<const ulonglong2*>(&sm.pc[buf][cb * 32]);
            const ulonglong2* vcp =
                reinterpret_cast<const ulonglong2*>(&sm.vc[buf][cb * 32]);
            const ulonglong2* x0p =
                reinterpret_cast<const ulonglong2*>(&sm.xs[k + 2][cb * 32]);
            const ulonglong2* x1p =
                reinterpret_cast<const ulonglong2*>(&sm.xs[k + 3][cb * 32]);
            unsigned long long rA0 = 0ull, rB0 = 0ull, rA1 = 0ull, rB1 = 0ull;
            #pragma unroll
            for (int q = 0; q < 8; q++) {
                const ulonglong2 p4 = pcp[q];
                const ulonglong2 v4 = vcp[q];
                const ulonglong2 x0 = x0p[q];
                const ulonglong2 x1 = x1p[q];
                FMA2(m[2*q],   nn1, p4.x, m[2*q]);
                FMA2(m[2*q],   nn2, v4.x, m[2*q]);
                FMA2(rA0, m[2*q], x0.x, rA0);
                FMA2(rA1, m[2*q], x1.x, rA1);
                FMA2(m[2*q+1], nn1, p4.y, m[2*q+1]);
                FMA2(m[2*q+1], nn2, v4.y, m[2*q+1]);
                FMA2(rB0, m[2*q+1], x0.y, rB0);
                FMA2(rB1, m[2*q+1], x1.y, rB1);
            }
            sm.part[buf ^ 1][0][row][cb] =
                (ull_lo(rA0) + ull_hi(rA0)) + (ull_lo(rB0) + ull_hi(rB0));
            sm.part[buf ^ 1][1][row][cb] =
                (ull_lo(rA1) + ull_hi(rA1)) + (ull_lo(rB1) + ull_hi(rB1));
        } else {
            // ===== S: correct staleness, 10-value reduce, scalar math =====
            float p0, p1, p2, p3, q0, q1, q2, q3;
            {
                const float4 r0 = *reinterpret_cast<const float4*>(sm.part[buf][0][i0 + 0]);
                const float4 r1 = *reinterpret_cast<const float4*>(sm.part[buf][0][i0 + 1]);
                const float4 r2 = *reinterpret_cast<const float4*>(sm.part[buf][0][i0 + 2]);
                const float4 r3 = *reinterpret_cast<const float4*>(sm.part[buf][0][i0 + 3]);
                p0 = (r0.x + r0.y) + (r0.z + r0.w) - cp0 * pp0 - cv0 * pv0;
                p1 = (r1.x + r1.y) + (r1.z + r1.w) - cp0 * pp1 - cv0 * pv1;
                p2 = (r2.x + r2.y) + (r2.z + r2.w) - cp0 * pp2 - cv0 * pv2;
                p3 = (r3.x + r3.y) + (r3.z + r3.w) - cp0 * pp3 - cv0 * pv3;
            }
            {
                const float4 r0 = *reinterpret_cast<const float4*>(sm.part[buf][1][i0 + 0]);
                const float4 r1 = *reinterpret_cast<const float4*>(sm.part[buf][1][i0 + 1]);
                const float4 r2 = *reinterpret_cast<const float4*>(sm.part[buf][1][i0 + 2]);
                const float4 r3 = *reinterpret_cast<const float4*>(sm.part[buf][1][i0 + 3]);
                q0 = (r0.x + r0.y) + (r0.z + r0.w) - cp1 * pp0 - cv1 * pv0;
                q1 = (r1.x + r1.y) + (r1.z + r1.w) - cp1 * pp1 - cv1 * pv1;
                q2 = (r2.x + r2.y) + (r2.z + r2.w) - cp1 * pp2 - cv1 * pv2;
                q3 = (r3.x + r3.y) + (r3.z + r3.w) - cp1 * pp3 - cv1 * pv3;
            }
            const float4 xk  = *reinterpret_cast<const float4*>(&sm.xs[k][i0]);
            const float4 xk1 = *reinterpret_cast<const float4*>(&sm.xs[k + 1][i0]);
            const float4 xk2 = *reinterpret_cast<const float4*>(&sm.xs[k + 2][i0]);
            const float4 xk3 = *reinterpret_cast<const float4*>(&sm.xs[k + 3][i0]);

            float s1  = (xk.x  * p0 + xk.y  * p1) + (xk.z  * p2 + xk.w  * p3);
            float cS  = (xk.x  * q0 + xk.y  * q1) + (xk.z  * q2 + xk.w  * q3);
            float s2  = (xk1.x * q0 + xk1.y * q1) + (xk1.z * q2 + xk1.w * q3);
            float ew0 = (xk.x  * w0 + xk.y  * w1) + (xk.z  * w2 + xk.w  * w3);
            float ew1 = (xk1.x * w0 + xk1.y * w1) + (xk1.z * w2 + xk1.w * w3);
            float ew2 = (xk2.x * w0 + xk2.y * w1) + (xk2.z * w2 + xk2.w * w3);
            float d1  = (xk2.x * p0 + xk2.y * p1) + (xk2.z * p2 + xk2.w * p3);
            float d2  = (xk2.x * q0 + xk2.y * q1) + (xk2.z * q2 + xk2.w * q3);
            float d3  = (xk3.x * p0 + xk3.y * p1) + (xk3.z * p2 + xk3.w * p3);
            float d4  = (xk3.x * q0 + xk3.y * q1) + (xk3.z * q2 + xk3.w * q3);

            #pragma unroll
            for (int off = 16; off > 0; off >>= 1) {
                s1  += __shfl_xor_sync(0xffffffffu, s1,  off);
                cS  += __shfl_xor_sync(0xffffffffu, cS,  off);
                s2  += __shfl_xor_sync(0xffffffffu, s2,  off);
                ew0 += __shfl_xor_sync(0xffffffffu, ew0, off);
                ew1 += __shfl_xor_sync(0xffffffffu, ew1, off);
                ew2 += __shfl_xor_sync(0xffffffffu, ew2, off);
                d1  += __shfl_xor_sync(0xffffffffu, d1,  off);
                d2  += __shfl_xor_sync(0xffffffffu, d2,  off);
                d3  += __shfl_xor_sync(0xffffffffu, d3,  off);
                d4  += __shfl_xor_sync(0xffffffffu, d4,  off);
            }

            const float inv1  = 1.0f / (1.0f + s1);
            const float coef0 = (sm.ts[k] - ew0) * inv1;
            const float cc    = cS * inv1;
            const float t2    = s2 - cS * cc;
            const float inv2  = 1.0f / (1.0f + t2);
            const float pred1 = fmaf(coef0, cS, ew1);
            const float coef1 = (sm.ts[k + 1] - pred1) * inv2;
            const float pred2 = ew2 + coef0 * d1 + coef1 * (d2 - cc * d1);

            // new v, w update
            const float nv0 = q0 - cc * p0, nv1 = q1 - cc * p1;
            const float nv2 = q2 - cc * p2, nv3 = q3 - cc * p3;
            w0 += coef0 * p0 + coef1 * nv0;
            w1 += coef0 * p1 + coef1 * nv1;
            w2 += coef0 * p2 + coef1 * nv2;
            w3 += coef0 * p3 + coef1 * nv3;

            const int nb = buf ^ 1;
            *reinterpret_cast<float4*>(&sm.pc[nb][i0]) = make_float4(p0, p1, p2, p3);
            *reinterpret_cast<float4*>(&sm.vc[nb][i0]) = make_float4(nv0, nv1, nv2, nv3);
            *reinterpret_cast<float4*>(&sm.au[nb][i0]) =
                make_float4(inv1 * p0, inv1 * p1, inv1 * p2, inv1 * p3);
            *reinterpret_cast<float4*>(&sm.bu[nb][i0]) =
                make_float4(inv2 * nv0, inv2 * nv1, inv2 * nv2, inv2 * nv3);

            if (lane == 0) {
                out[(size_t)b * NPTS + k + 1] = pred1;
                if (k + 2 < NPTS) out[(size_t)b * NPTS + k + 2] = pred2;
            }

            // carry to next block
            pp0 = p0; pp1 = p1; pp2 = p2; pp3 = p3;
            pv0 = nv0; pv1 = nv1; pv2 = nv2; pv3 = nv3;
            cp0 = inv1 * d1;  cv0 = inv2 * (d2 - cc * d1);
            cp1 = inv1 * d3;  cv1 = inv2 * (d4 - cc * d3);
        }
        __syncthreads();
        buf ^= 1;
    }
}

extern "C" void kernel_launch(void* const* d_in, const int* in_sizes, int n_in,
                              void* d_out, int out_size)
{
    const float* data    = (const float*)d_in[0];   // [32, 256, 128] f32
    const float* targets = (const float*)d_in[1];   // [32, 256]      f32
    float* out = (float*)d_out;                     // [32, 256]      f32

    const size_t smem_bytes = sizeof(SMLayout);
    cudaFuncSetAttribute(ridge_rls2_kernel,
                         cudaFuncAttributeMaxDynamicSharedMemorySize,
                         (int)smem_bytes);
    ridge_rls2_kernel<<<BATCH, TOT, smem_bytes>>>(data, targets, out);
}